// round 1
// baseline (speedup 1.0000x reference)
#include <cuda_runtime.h>
#include <math.h>

#define BB 64
#define CIN 256
#define COUT 256
#define HH 64
#define WW 64
#define NB 8
#define HID 128
#define HWPIX 4096

#define TILE_H 16
#define CONV_THREADS 128
#define XS_ROWS 18
#define XS_COLS 66
#define XS_ELEMS (XS_ROWS * XS_COLS)   /* 1188 */
#define NLD 10
#define FS_ELEMS (CIN * NB * 9)        /* 18432 */

// -------- scratch (no cudaMalloc allowed) --------
__device__ __align__(16) float g_pooled[BB * CIN];
__device__ __align__(16) float g_mix[BB * COUT * NB];
__device__ __align__(16) float g_y[(size_t)BB * NB * HWPIX];

// -------- packed f32x2 helpers (sm_103a) --------
static __device__ __forceinline__ unsigned long long pk2(float lo, float hi) {
    unsigned long long r;
    asm("mov.b64 %0, {%1, %2};" : "=l"(r) : "f"(lo), "f"(hi));
    return r;
}
static __device__ __forceinline__ void upk2(unsigned long long v, float &lo, float &hi) {
    asm("mov.b64 {%0, %1}, %2;" : "=f"(lo), "=f"(hi) : "l"(v));
}
static __device__ __forceinline__ unsigned long long fma2(
    unsigned long long a, unsigned long long b, unsigned long long c) {
    unsigned long long d;
    asm("fma.rn.f32x2 %0, %1, %2, %3;" : "=l"(d) : "l"(a), "l"(b), "l"(c));
    return d;
}

// -------- kernel 1: zero pooled scratch --------
__global__ void zero_kernel() {
    int i = blockIdx.x * blockDim.x + threadIdx.x;
    if (i < BB * CIN) g_pooled[i] = 0.f;
}

// -------- kernel 2: fused 3x3 conv (8 base filters) + global-avg-pool partials --------
// Grid: 64 b * 4 h-tiles = 256 CTAs, 128 threads.
// Thread t: row r = t/8 within tile, 8 consecutive w pixels (4 f32x2 pairs), 8 filters.
__global__ __launch_bounds__(CONV_THREADS)
void conv_pool_kernel(const float* __restrict__ x, const float* __restrict__ bf) {
    extern __shared__ float smem[];
    float* fs = smem;                 // [CIN][NB*9] filters, 72KB
    float* xs = smem + FS_ELEMS;      // [18][66] single-channel tile + halo

    const int t     = threadIdx.x;
    const int b     = blockIdx.x >> 2;
    const int h0    = (blockIdx.x & 3) * TILE_H;
    const int r     = t >> 3;
    const int wbase = (t & 7) * 8;

    // one-time: filters into smem, layout fs[c*72 + n*9 + tap]
    for (int i = t; i < FS_ELEMS; i += CONV_THREADS) {
        int c = i / 72, rr = i % 72, n = rr / 9, tap = rr % 9;
        fs[i] = bf[n * 2304 + c * 9 + tap];
    }

    // precompute per-thread load slots for the 1188-elem tile
    int  offk[NLD];
    bool vk[NLD], pmk[NLD];
#pragma unroll
    for (int k = 0; k < NLD; k++) {
        int idx = t + k * CONV_THREADS;
        vk[k] = false; pmk[k] = false; offk[k] = 0;
        if (idx < XS_ELEMS) {
            int row = idx / XS_COLS, col = idx % XS_COLS;
            int gh = h0 - 1 + row, gw = col - 1;
            if (gh >= 0 && gh < HH && gw >= 0 && gw < WW) {
                vk[k]  = true;
                offk[k] = gh * WW + gw;
                // interior (non-halo) elements contribute to the pool sum exactly once
                pmk[k] = (row >= 1 && row <= TILE_H && col >= 1 && col <= WW);
            }
        }
    }
    const float* xb = x + (size_t)b * CIN * HWPIX;

    // software pipeline: prefetch channel 0
    float ld[NLD];
#pragma unroll
    for (int k = 0; k < NLD; k++) ld[k] = vk[k] ? __ldg(xb + offk[k]) : 0.f;

    unsigned long long acc[NB][4];
#pragma unroll
    for (int n = 0; n < NB; n++)
#pragma unroll
        for (int j = 0; j < 4; j++) acc[n][j] = 0ULL;

    for (int c = 0; c < CIN; c++) {
        __syncthreads();  // previous tile's reads complete (also covers filter stores on c=0)
        float ps = 0.f;
#pragma unroll
        for (int k = 0; k < NLD; k++) {
            int idx = t + k * CONV_THREADS;
            if (idx < XS_ELEMS) xs[idx] = ld[k];
            if (pmk[k]) ps += ld[k];
        }
        __syncthreads();  // tile c ready

        // pooled partial for channel c (warp reduce + one atomic per warp)
#pragma unroll
        for (int o = 16; o > 0; o >>= 1) ps += __shfl_down_sync(0xffffffffu, ps, o);
        if ((t & 31) == 0) atomicAdd(&g_pooled[b * CIN + c], ps);

        // prefetch channel c+1 (hides DRAM latency under the FMA phase)
        if (c + 1 < CIN) {
            const float* xc = xb + (size_t)(c + 1) * HWPIX;
#pragma unroll
            for (int k = 0; k < NLD; k++) ld[k] = vk[k] ? __ldg(xc + offk[k]) : 0.f;
        }

        // compute: 8 filters * 9 taps * 4 pixel-pairs = 288 packed FMAs / thread / channel
        const float* fc = fs + c * 72;
#pragma unroll
        for (int dy = 0; dy < 3; dy++) {
            float xr[10];
            const float* xrow = xs + (r + dy) * XS_COLS + wbase;
#pragma unroll
            for (int i = 0; i < 10; i++) xr[i] = xrow[i];
            unsigned long long P[3][4];
#pragma unroll
            for (int j = 0; j < 4; j++) {
                P[0][j] = pk2(xr[2 * j],     xr[2 * j + 1]);  // dx = -1
                P[1][j] = pk2(xr[2 * j + 1], xr[2 * j + 2]);  // dx =  0
                P[2][j] = pk2(xr[2 * j + 2], xr[2 * j + 3]);  // dx = +1
            }
#pragma unroll
            for (int n = 0; n < NB; n++) {
                const float* fp = fc + n * 9 + dy * 3;
                unsigned long long f0 = pk2(fp[0], fp[0]);
                unsigned long long f1 = pk2(fp[1], fp[1]);
                unsigned long long f2 = pk2(fp[2], fp[2]);
#pragma unroll
                for (int j = 0; j < 4; j++) {
                    acc[n][j] = fma2(P[0][j], f0, acc[n][j]);
                    acc[n][j] = fma2(P[1][j], f1, acc[n][j]);
                    acc[n][j] = fma2(P[2][j], f2, acc[n][j]);
                }
            }
        }
    }

    // write y[b,n,h0+r, wbase..wbase+7] as two float4s
#pragma unroll
    for (int n = 0; n < NB; n++) {
        float v[8];
#pragma unroll
        for (int j = 0; j < 4; j++) upk2(acc[n][j], v[2 * j], v[2 * j + 1]);
        float* yp = g_y + ((size_t)(b * NB + n) * HH + (h0 + r)) * WW + wbase;
        *(float4*)(yp)     = make_float4(v[0], v[1], v[2], v[3]);
        *(float4*)(yp + 4) = make_float4(v[4], v[5], v[6], v[7]);
    }
}

// -------- kernel 3: attention MLP + softmax -> mix[b, o, n] --------
// 64 blocks (one per b), 256 threads (one per output channel o in stage 3)
__global__ __launch_bounds__(COUT)
void mlp_kernel(const float* __restrict__ w1, const float* __restrict__ b1,
                const float* __restrict__ w2, const float* __restrict__ b2) {
    __shared__ float psm[CIN];
    __shared__ float hs[HID];
    const int b = blockIdx.x, t = threadIdx.x;

    psm[t] = g_pooled[b * CIN + t] * (1.f / (float)HWPIX);
    __syncthreads();

    if (t < HID) {
        float a = b1[t];
        const float* wr = w1 + t * CIN;
        for (int c = 0; c < CIN; c++) a = fmaf(psm[c], wr[c], a);
        hs[t] = fmaxf(a, 0.f);
    }
    __syncthreads();

    // t = o: 8 dot-products of length 128, then softmax over n
    float v[NB];
#pragma unroll
    for (int n = 0; n < NB; n++) v[n] = b2[t * NB + n];
    const float* w2b = w2 + (size_t)t * NB * HID;
    for (int k = 0; k < HID; k++) {
        float h = hs[k];
#pragma unroll
        for (int n = 0; n < NB; n++) v[n] = fmaf(h, w2b[n * HID + k], v[n]);
    }
    float m = v[0];
#pragma unroll
    for (int n = 1; n < NB; n++) m = fmaxf(m, v[n]);
    float e[NB], s = 0.f;
#pragma unroll
    for (int n = 0; n < NB; n++) { e[n] = expf(v[n] - m); s += e[n]; }
    float inv = 1.f / s;
#pragma unroll
    for (int n = 0; n < NB; n++) g_mix[b * COUT * NB + t * NB + n] = e[n] * inv;
}

// -------- kernel 4: out[b,o,p] = sum_n mix[b,o,n] * y[b,n,p] --------
// Grid: 64 b * 4 pixel-chunks = 256 CTAs, 256 threads; thread owns 4 contiguous pixels.
__global__ __launch_bounds__(256)
void apply_kernel(float* __restrict__ out) {
    __shared__ __align__(16) float ms[COUT * NB];
    const int b = blockIdx.x >> 2, t = threadIdx.x;
    const int p0 = (blockIdx.x & 3) * 1024 + t * 4;

    for (int i = t; i < COUT * NB; i += 256) ms[i] = g_mix[b * COUT * NB + i];
    __syncthreads();

    unsigned long long y2[NB][2];
#pragma unroll
    for (int n = 0; n < NB; n++) {
        float4 v = *(const float4*)(g_y + (size_t)(b * NB + n) * HWPIX + p0);
        y2[n][0] = pk2(v.x, v.y);
        y2[n][1] = pk2(v.z, v.w);
    }

    float* ob = out + (size_t)b * COUT * HWPIX + p0;
    for (int o = 0; o < COUT; o++) {
        const float4 m0 = *(const float4*)(ms + o * NB);
        const float4 m1 = *(const float4*)(ms + o * NB + 4);
        float mv[8] = {m0.x, m0.y, m0.z, m0.w, m1.x, m1.y, m1.z, m1.w};
        unsigned long long a0 = 0ULL, a1 = 0ULL;
#pragma unroll
        for (int n = 0; n < NB; n++) {
            unsigned long long fb = pk2(mv[n], mv[n]);
            a0 = fma2(y2[n][0], fb, a0);
            a1 = fma2(y2[n][1], fb, a1);
        }
        float o0, o1, o2, o3;
        upk2(a0, o0, o1);
        upk2(a1, o2, o3);
        *(float4*)(ob + (size_t)o * HWPIX) = make_float4(o0, o1, o2, o3);
    }
}

extern "C" void kernel_launch(void* const* d_in, const int* in_sizes, int n_in,
                              void* d_out, int out_size) {
    const float* x  = (const float*)d_in[0];
    const float* w1 = (const float*)d_in[1];
    const float* b1 = (const float*)d_in[2];
    const float* w2 = (const float*)d_in[3];
    const float* b2 = (const float*)d_in[4];
    const float* bf = (const float*)d_in[5];
    float* out = (float*)d_out;

    const int smem_bytes = (FS_ELEMS + XS_ELEMS) * (int)sizeof(float);  // ~78.5 KB
    cudaFuncSetAttribute(conv_pool_kernel,
                         cudaFuncAttributeMaxDynamicSharedMemorySize, smem_bytes);

    zero_kernel<<<(BB * CIN + 255) / 256, 256>>>();
    conv_pool_kernel<<<BB * 4, CONV_THREADS, smem_bytes>>>(x, bf);
    mlp_kernel<<<BB, COUT>>>(w1, b1, w2, b2);
    apply_kernel<<<BB * 4, 256>>>(out);
}